// round 4
// baseline (speedup 1.0000x reference)
#include <cuda_runtime.h>
#include <cstdint>
#include <cstddef>

// ---------------------------------------------------------------------------
// WaveNet gated residual block on sm_103 (baseline PTX only — tcgen05 is
// sm_103a-accelerated and the harness compiles via compute_103, so we use
// Ampere-style mma.sync tf32 with register accumulators).
//
//   gate : D1[BT,512] = A[BT,256(prev|cur)] x Wg[512,256]^T
//   m    = tanh(D1[:, :256]+bt) * sigmoid(D1[:,256:]+bs)     (tf32-rounded)
//   out  : D2[BT,384] = m x Wo[384,256]^T
//   res  = D2[:, :128]+br+x ; skip = D2[:,128:]+bk
// ---------------------------------------------------------------------------

#define DEVFN __device__ __forceinline__

static constexpr int NST      = 3;
static constexpr int STAGE_F  = 12288;           // floats per stage (48 KB)
static constexpr int SMEM_BYTES = NST * 49152;   // 147456

__device__ float wscratch[(512 + 384) * 256];    // packed tf32 weights (896 KB)
__device__ float mscratch[131072 * 256];         // gated activations m (128 MB)

// ------------------------------- helpers -----------------------------------
DEVFN uint32_t smaddr(const void* p) {
    uint32_t a;
    asm("{ .reg .u64 t; cvta.to.shared.u64 t, %1; cvt.u32.u64 %0, t; }" : "=r"(a) : "l"(p));
    return a;
}
DEVFN uint32_t tf32r(float x) { uint32_t u; asm("cvt.rna.tf32.f32 %0, %1;" : "=r"(u) : "f"(x)); return u; }
DEVFN float ex2f(float x) { float y; asm("ex2.approx.ftz.f32 %0, %1;" : "=f"(y) : "f"(x)); return y; }
DEVFN float rcpf(float x) { float y; asm("rcp.approx.ftz.f32 %0, %1;" : "=f"(y) : "f"(x)); return y; }
DEVFN float sigm(float v)  { return rcpf(1.0f + ex2f(-1.4426950408889634f * v)); }
DEVFN float tanha(float v) { return 1.0f - 2.0f * rcpf(1.0f + ex2f(2.8853900817779268f * v)); }

DEVFN void cpa16(uint32_t dst, const void* src, int sz) {
    asm volatile("cp.async.cg.shared.global [%0], [%1], 16, %2;"
                 :: "r"(dst), "l"(src), "r"(sz) : "memory");
}
DEVFN void cpcommit() { asm volatile("cp.async.commit_group;" ::: "memory"); }
#define CPWAIT(n) asm volatile("cp.async.wait_group %0;" :: "n"(n) : "memory")

// m16n8k8 tf32 mma, row.col, f32 accum
DEVFN void mma8(float* d, const uint32_t* a, const uint32_t* b) {
    asm("mma.sync.aligned.m16n8k8.row.col.f32.tf32.tf32.f32 "
        "{%0,%1,%2,%3}, {%4,%5,%6,%7}, {%8,%9}, {%0,%1,%2,%3};"
        : "+f"(d[0]), "+f"(d[1]), "+f"(d[2]), "+f"(d[3])
        : "r"(a[0]), "r"(a[1]), "r"(a[2]), "r"(a[3]), "r"(b[0]), "r"(b[1]));
}

// ------------------------- weight packing kernel ---------------------------
// wscratch[n][k] (256 k floats per row, tf32-rounded):
//   n <  256 : gate tanh col n   ; k<128 -> w_tanh[tap0][k][n], k>=128 -> tap1
//   n <  512 : gate sig col n-256
//   n <  640 : out res col        (w_res[0][k][n-512])
//   n <  896 : out skip col       (w_skip[0][k][n-640])
__global__ void pack_w(const float* __restrict__ wt, const float* __restrict__ ws,
                       const float* __restrict__ wr, const float* __restrict__ wk) {
    int idx = blockIdx.x * 256 + threadIdx.x;
    if (idx >= 896 * 256) return;
    int n = idx >> 8, k = idx & 255;
    float v;
    if (n < 512) {
        int tap = k >> 7, c = k & 127;
        v = (n < 256) ? wt[(tap * 128 + c) * 256 + n]
                      : ws[(tap * 128 + c) * 256 + (n - 256)];
    } else {
        int nn = n - 512;
        v = (nn < 128) ? wr[k * 128 + nn]
                       : wk[k * 256 + (nn - 128)];
    }
    wscratch[idx] = __uint_as_float(tf32r(v));
}

// ------------------------------ gate kernel --------------------------------
// grid 2048: mt = bid & 1023 (128-token tile), cg = bid >> 10 (column group).
// CTA 256 thr = 8 warps (2M x 4N), warp tile 64x64.
// N cols: nwarp 0,1 -> tanh cols cg*128 + [0,128) ; nwarp 2,3 -> sig same cols.
__global__ void __launch_bounds__(256, 1)
gate_kernel(const float* __restrict__ x,
            const float* __restrict__ bt, const float* __restrict__ bs) {
    extern __shared__ float sm[];
    uint32_t sb = smaddr(sm);
    int tid = threadIdx.x, wid = tid >> 5, lid = tid & 31;
    int mt = blockIdx.x & 1023;
    int cg = blockIdx.x >> 10;
    long g0 = (long)mt * 128;
    bool head = (mt & 127) == 0;      // first tile in a batch row (T=16384)

    int mwarp = wid >> 2;             // 0..1
    int nwarp = wid & 3;              // 0..3
    int r0 = lid >> 2, c0 = lid & 3;

    auto load_chunk = [&](int kc, int st) {
        uint32_t abase = sb + st * 49152;
        uint32_t bbase = abase + 16384;
        // A: 128 rows x 32 k floats (8 x 16B groups), XOR swizzle by row&7
#pragma unroll
        for (int i = 0; i < 4; ++i) {
            int idx = tid + i * 256;
            int row = idx >> 3, g = idx & 7;
            const float* src = x;
            int sz = 16;
            if (kc < 4) {
                if (head && row < 4) sz = 0;
                else src = x + (g0 + row - 4) * 128 + kc * 32 + g * 4;
            } else {
                src = x + (g0 + row) * 128 + (kc - 4) * 32 + g * 4;
            }
            cpa16(abase + row * 128 + 16 * (g ^ (row & 7)), src, sz);
        }
        // B: 256 rows (tanh 128 | sig 128)
#pragma unroll
        for (int i = 0; i < 8; ++i) {
            int idx = tid + i * 256;
            int row = idx >> 3, g = idx & 7;
            int ngl = (row < 128) ? (cg * 128 + row) : (256 + cg * 128 + (row - 128));
            const float* src = wscratch + ngl * 256 + kc * 32 + g * 4;
            cpa16(bbase + row * 128 + 16 * (g ^ (row & 7)), src, 16);
        }
    };

    float acc[4][8][4];
#pragma unroll
    for (int i = 0; i < 4; ++i)
#pragma unroll
        for (int j = 0; j < 8; ++j)
#pragma unroll
            for (int q = 0; q < 4; ++q) acc[i][j][q] = 0.0f;

    load_chunk(0, 0); cpcommit();
    load_chunk(1, 1); cpcommit();

    for (int kc = 0; kc < 8; ++kc) {
        CPWAIT(1);
        __syncthreads();
        if (kc + 2 < 8) load_chunk(kc + 2, (kc + 2) % 3);
        cpcommit();
        int aoff = (kc % 3) * STAGE_F;
        int boff = aoff + 4096;
#pragma unroll
        for (int ks = 0; ks < 4; ++ks) {
            uint32_t a[4][4];
#pragma unroll
            for (int mf = 0; mf < 4; ++mf) {
                int row = mwarp * 64 + mf * 16 + r0;
                int swz = (row & 7) << 2;
                int rb  = aoff + row * 32;
                int k0  = ks * 8 + c0;
                a[mf][0] = tf32r(sm[rb           + (k0 ^ swz)]);
                a[mf][1] = tf32r(sm[rb + 8 * 32  + (k0 ^ swz)]);
                a[mf][2] = tf32r(sm[rb           + ((k0 + 4) ^ swz)]);
                a[mf][3] = tf32r(sm[rb + 8 * 32  + ((k0 + 4) ^ swz)]);
            }
            uint32_t b[8][2];
#pragma unroll
            for (int nf = 0; nf < 8; ++nf) {
                int n = nwarp * 64 + nf * 8 + r0;
                int swz = (n & 7) << 2;
                int nb = boff + n * 32;
                int k0 = ks * 8 + c0;
                b[nf][0] = __float_as_uint(sm[nb + (k0 ^ swz)]);
                b[nf][1] = __float_as_uint(sm[nb + ((k0 + 4) ^ swz)]);
            }
#pragma unroll
            for (int mf = 0; mf < 4; ++mf)
#pragma unroll
                for (int nf = 0; nf < 8; ++nf)
                    mma8(acc[mf][nf], a[mf], b[nf]);
        }
    }

    // ---- epilogue: m = tanh * sigmoid via SMEM exchange ----
    __syncthreads();
    if (nwarp >= 2) {   // sigmoid half -> staging (row stride 132 floats)
#pragma unroll
        for (int mf = 0; mf < 4; ++mf) {
#pragma unroll
            for (int nf = 0; nf < 8; ++nf) {
                int colL = (nwarp - 2) * 64 + nf * 8 + c0 * 2;
                float bv0 = __ldg(bs + cg * 128 + colL);
                float bv1 = __ldg(bs + cg * 128 + colL + 1);
                int row = mwarp * 64 + mf * 16 + r0;
                sm[row * 132 + colL]           = sigm(acc[mf][nf][0] + bv0);
                sm[row * 132 + colL + 1]       = sigm(acc[mf][nf][1] + bv1);
                sm[(row + 8) * 132 + colL]     = sigm(acc[mf][nf][2] + bv0);
                sm[(row + 8) * 132 + colL + 1] = sigm(acc[mf][nf][3] + bv1);
            }
        }
    }
    __syncthreads();
    if (nwarp < 2) {    // tanh half -> multiply, round to tf32, store m
#pragma unroll
        for (int mf = 0; mf < 4; ++mf) {
#pragma unroll
            for (int nf = 0; nf < 8; ++nf) {
                int colL = nwarp * 64 + nf * 8 + c0 * 2;
                float bv0 = __ldg(bt + cg * 128 + colL);
                float bv1 = __ldg(bt + cg * 128 + colL + 1);
                int row = mwarp * 64 + mf * 16 + r0;
                float m00 = tanha(acc[mf][nf][0] + bv0) * sm[row * 132 + colL];
                float m01 = tanha(acc[mf][nf][1] + bv1) * sm[row * 132 + colL + 1];
                float m10 = tanha(acc[mf][nf][2] + bv0) * sm[(row + 8) * 132 + colL];
                float m11 = tanha(acc[mf][nf][3] + bv1) * sm[(row + 8) * 132 + colL + 1];
                float2 v0 = make_float2(__uint_as_float(tf32r(m00)), __uint_as_float(tf32r(m01)));
                float2 v1 = make_float2(__uint_as_float(tf32r(m10)), __uint_as_float(tf32r(m11)));
                *(float2*)(mscratch + (g0 + row) * 256 + cg * 128 + colL)       = v0;
                *(float2*)(mscratch + (g0 + row + 8) * 256 + cg * 128 + colL)   = v1;
            }
        }
    }
}

// ------------------------------ out kernel ---------------------------------
// grid 1536: mt = bid % 512 (256-token tile), ng = bid / 512 (N group of 128).
// CTA 256 thr = 8 warps (4M x 2N), warp tile 64x64.
__global__ void __launch_bounds__(256, 1)
out_kernel(const float* __restrict__ x,
           const float* __restrict__ br, const float* __restrict__ bk,
           float* __restrict__ out) {
    extern __shared__ float sm[];
    uint32_t sb = smaddr(sm);
    int tid = threadIdx.x, wid = tid >> 5, lid = tid & 31;
    int mt = blockIdx.x & 511;
    int ng = blockIdx.x >> 9;
    long g0 = (long)mt * 256;

    int mwarp = wid & 3;              // 0..3
    int nwarp = wid >> 2;             // 0..1
    int r0 = lid >> 2, c0 = lid & 3;

    auto load_chunk = [&](int kc, int st) {
        uint32_t abase = sb + st * 49152;
        uint32_t bbase = abase + 32768;
        // A = m : 256 rows x 32 k
#pragma unroll
        for (int i = 0; i < 8; ++i) {
            int idx = tid + i * 256;
            int row = idx >> 3, g = idx & 7;
            const float* src = mscratch + (g0 + row) * 256 + kc * 32 + g * 4;
            cpa16(abase + row * 128 + 16 * (g ^ (row & 7)), src, 16);
        }
        // B : 128 rows
#pragma unroll
        for (int i = 0; i < 4; ++i) {
            int idx = tid + i * 256;
            int row = idx >> 3, g = idx & 7;
            const float* src = wscratch + (512 + ng * 128 + row) * 256 + kc * 32 + g * 4;
            cpa16(bbase + row * 128 + 16 * (g ^ (row & 7)), src, 16);
        }
    };

    float acc[4][8][4];
#pragma unroll
    for (int i = 0; i < 4; ++i)
#pragma unroll
        for (int j = 0; j < 8; ++j)
#pragma unroll
            for (int q = 0; q < 4; ++q) acc[i][j][q] = 0.0f;

    load_chunk(0, 0); cpcommit();
    load_chunk(1, 1); cpcommit();

    for (int kc = 0; kc < 8; ++kc) {
        CPWAIT(1);
        __syncthreads();
        if (kc + 2 < 8) load_chunk(kc + 2, (kc + 2) % 3);
        cpcommit();
        int aoff = (kc % 3) * STAGE_F;
        int boff = aoff + 8192;
#pragma unroll
        for (int ks = 0; ks < 4; ++ks) {
            uint32_t a[4][4];
#pragma unroll
            for (int mf = 0; mf < 4; ++mf) {
                int row = mwarp * 64 + mf * 16 + r0;
                int swz = (row & 7) << 2;
                int rb  = aoff + row * 32;
                int k0  = ks * 8 + c0;
                a[mf][0] = __float_as_uint(sm[rb          + (k0 ^ swz)]);
                a[mf][1] = __float_as_uint(sm[rb + 8 * 32 + (k0 ^ swz)]);
                a[mf][2] = __float_as_uint(sm[rb          + ((k0 + 4) ^ swz)]);
                a[mf][3] = __float_as_uint(sm[rb + 8 * 32 + ((k0 + 4) ^ swz)]);
            }
            uint32_t b[8][2];
#pragma unroll
            for (int nf = 0; nf < 8; ++nf) {
                int n = nwarp * 64 + nf * 8 + r0;
                int swz = (n & 7) << 2;
                int nb = boff + n * 32;
                int k0 = ks * 8 + c0;
                b[nf][0] = __float_as_uint(sm[nb + (k0 ^ swz)]);
                b[nf][1] = __float_as_uint(sm[nb + ((k0 + 4) ^ swz)]);
            }
#pragma unroll
            for (int mf = 0; mf < 4; ++mf)
#pragma unroll
                for (int nf = 0; nf < 8; ++nf)
                    mma8(acc[mf][nf], a[mf], b[nf]);
        }
    }

    // ---- epilogue: bias (+ residual) and store ----
    float* outR = out;                                  // [131072,128]
    float* outK = out + (size_t)131072 * 128;           // [131072,256]
#pragma unroll
    for (int mf = 0; mf < 4; ++mf) {
#pragma unroll
        for (int nf = 0; nf < 8; ++nf) {
            int colG = ng * 128 + nwarp * 64 + nf * 8 + c0 * 2;
            long row0 = g0 + mwarp * 64 + mf * 16 + r0;
            long row1 = row0 + 8;
            if (ng == 0) {
                float bv0 = __ldg(br + colG), bv1 = __ldg(br + colG + 1);
                float2 x0 = *(const float2*)(x + row0 * 128 + colG);
                float2 x1 = *(const float2*)(x + row1 * 128 + colG);
                float2 o0 = make_float2(acc[mf][nf][0] + bv0 + x0.x,
                                        acc[mf][nf][1] + bv1 + x0.y);
                float2 o1 = make_float2(acc[mf][nf][2] + bv0 + x1.x,
                                        acc[mf][nf][3] + bv1 + x1.y);
                *(float2*)(outR + row0 * 128 + colG) = o0;
                *(float2*)(outR + row1 * 128 + colG) = o1;
            } else {
                int colK = colG - 128;
                float bv0 = __ldg(bk + colK), bv1 = __ldg(bk + colK + 1);
                float2 o0 = make_float2(acc[mf][nf][0] + bv0, acc[mf][nf][1] + bv1);
                float2 o1 = make_float2(acc[mf][nf][2] + bv0, acc[mf][nf][3] + bv1);
                *(float2*)(outK + row0 * 256 + colK) = o0;
                *(float2*)(outK + row1 * 256 + colK) = o1;
            }
        }
    }
}

// ------------------------------- launch ------------------------------------
extern "C" void kernel_launch(void* const* d_in, const int* in_sizes, int n_in,
                              void* d_out, int out_size) {
    const float* x  = (const float*)d_in[0];
    const float* wt = (const float*)d_in[1];
    const float* bt = (const float*)d_in[2];
    const float* ws = (const float*)d_in[3];
    const float* bs = (const float*)d_in[4];
    const float* wr = (const float*)d_in[5];
    const float* br = (const float*)d_in[6];
    const float* wk = (const float*)d_in[7];
    const float* bk = (const float*)d_in[8];
    float* out = (float*)d_out;

    cudaFuncSetAttribute(gate_kernel, cudaFuncAttributeMaxDynamicSharedMemorySize, SMEM_BYTES);
    cudaFuncSetAttribute(out_kernel,  cudaFuncAttributeMaxDynamicSharedMemorySize, SMEM_BYTES);

    pack_w<<<896, 256>>>(wt, ws, wr, wk);
    gate_kernel<<<2048, 256, SMEM_BYTES>>>(x, bt, bs);
    out_kernel<<<1536, 256, SMEM_BYTES>>>(x, br, bk, out);
}